// round 10
// baseline (speedup 1.0000x reference)
#include <cuda_runtime.h>

// FINAL (converged, 4x reproduced): y = (W1*x > W0*x) ? +1 : -1 elementwise
// over 37.75M floats.
// (Reference: flat x @ W^T -> argmax over 2 logits -> 2*idx-1. With first-max
// tie-break, idx=1 iff W1*x > W0*x; exact fp32 mults preserved -> rel_err 0.)
//
// Pure HBM streaming: 151MB read + 151MB write. 302MB in 40.1us = 7.52 TB/s,
// 94% of the 8TB/s HBM3e spec — at the memory roofline. Timed dur_us floor
// ~49.1 (kernel + ~8.9us fixed graph-replay overhead), noise ±0.15us.
//
// Config sweep (kernel time / DRAM busy) — optimum verified on all axes:
//   256x1-2: 42.4/75.6   512x8: 42.0/74.0   128x2: 41.8/74.6
//   64x4:    40.9/76.3   256x4: 40.8/76.4   128x4: 40.13/77.7  <== this
//
// 128 threads/block, 4 front-batched float4 loads/thread (MLP_p1=4),
// streaming cache hints (.cs — zero reuse). Grid = 18432 for the benchmark
// shape (exactly divisible -> guard-free hot path); edge/tail paths kept for
// arbitrary-shape safety.

__global__ void __launch_bounds__(128)
metaconv_sign4x128_kernel(const float4* __restrict__ x,
                          const float* __restrict__ W,
                          float4* __restrict__ out,
                          int n4) {
    const float w0 = W[0];
    const float w1 = W[1];

    const int base = blockIdx.x * (128 * 4) + threadIdx.x;
    const int i0 = base;
    const int i1 = base + 128;
    const int i2 = base + 256;
    const int i3 = base + 384;

    if (i3 < n4) {
        float4 v0 = __ldcs(&x[i0]);
        float4 v1 = __ldcs(&x[i1]);
        float4 v2 = __ldcs(&x[i2]);
        float4 v3 = __ldcs(&x[i3]);

        float4 r0, r1, r2, r3;
        r0.x = (w1 * v0.x > w0 * v0.x) ? 1.0f : -1.0f;
        r0.y = (w1 * v0.y > w0 * v0.y) ? 1.0f : -1.0f;
        r0.z = (w1 * v0.z > w0 * v0.z) ? 1.0f : -1.0f;
        r0.w = (w1 * v0.w > w0 * v0.w) ? 1.0f : -1.0f;
        r1.x = (w1 * v1.x > w0 * v1.x) ? 1.0f : -1.0f;
        r1.y = (w1 * v1.y > w0 * v1.y) ? 1.0f : -1.0f;
        r1.z = (w1 * v1.z > w0 * v1.z) ? 1.0f : -1.0f;
        r1.w = (w1 * v1.w > w0 * v1.w) ? 1.0f : -1.0f;
        r2.x = (w1 * v2.x > w0 * v2.x) ? 1.0f : -1.0f;
        r2.y = (w1 * v2.y > w0 * v2.y) ? 1.0f : -1.0f;
        r2.z = (w1 * v2.z > w0 * v2.z) ? 1.0f : -1.0f;
        r2.w = (w1 * v2.w > w0 * v2.w) ? 1.0f : -1.0f;
        r3.x = (w1 * v3.x > w0 * v3.x) ? 1.0f : -1.0f;
        r3.y = (w1 * v3.y > w0 * v3.y) ? 1.0f : -1.0f;
        r3.z = (w1 * v3.z > w0 * v3.z) ? 1.0f : -1.0f;
        r3.w = (w1 * v3.w > w0 * v3.w) ? 1.0f : -1.0f;

        __stcs(&out[i0], r0);
        __stcs(&out[i1], r1);
        __stcs(&out[i2], r2);
        __stcs(&out[i3], r3);
    } else {
        #pragma unroll
        for (int k = 0; k < 4; k++) {
            int i = base + k * 128;
            if (i < n4) {
                float4 v = __ldcs(&x[i]);
                float4 r;
                r.x = (w1 * v.x > w0 * v.x) ? 1.0f : -1.0f;
                r.y = (w1 * v.y > w0 * v.y) ? 1.0f : -1.0f;
                r.z = (w1 * v.z > w0 * v.z) ? 1.0f : -1.0f;
                r.w = (w1 * v.w > w0 * v.w) ? 1.0f : -1.0f;
                __stcs(&out[i], r);
            }
        }
    }
}

// Scalar tail kernel in case N % 4 != 0 (not needed for this shape, but safe).
__global__ void metaconv_sign_tail(const float* __restrict__ x,
                                   const float* __restrict__ W,
                                   float* __restrict__ out,
                                   int start, int n) {
    const float w0 = W[0];
    const float w1 = W[1];
    int i = start + blockIdx.x * blockDim.x + threadIdx.x;
    if (i < n) {
        float v = x[i];
        out[i] = (w1 * v > w0 * v) ? 1.0f : -1.0f;
    }
}

extern "C" void kernel_launch(void* const* d_in, const int* in_sizes, int n_in,
                              void* d_out, int out_size) {
    const float* x = (const float*)d_in[0];
    const float* W = (const float*)d_in[1];
    float* out = (float*)d_out;

    const int n = in_sizes[0];
    const int n4 = n >> 2;

    if (n4 > 0) {
        const int threads = 128;
        const int per_block = threads * 4;  // float4s per block
        int blocks = (n4 + per_block - 1) / per_block;
        metaconv_sign4x128_kernel<<<blocks, threads>>>(
            (const float4*)x, W, (float4*)out, n4);
    }
    const int rem = n - (n4 << 2);
    if (rem > 0) {
        metaconv_sign_tail<<<1, 32>>>(x, W, out, n4 << 2, n);
    }
}